// round 1
// baseline (speedup 1.0000x reference)
#include <cuda_runtime.h>
#include <cuda_bf16.h>

#define N_NODES 40000
#define N_EDGES 480000
#define NPLANE  (N_NODES * 64)

__device__ __align__(16) float g_hs[N_NODES * 64];        // h_s [N][64]
__device__ __align__(16) float g_hv[3 * N_NODES * 64];    // h_v c-major: [3][N][64]
__device__ __align__(16) float g_sc[N_NODES * 320];       // sc_s [128] then sc_v [o*3+c]
__device__ __align__(16) float g_agg[(size_t)N_NODES * 512]; // [128 scalars][3][128] c-major vectors

__device__ __forceinline__ float swishf(float x) {
    return x / (1.0f + __expf(-x));
}

// ---------------- constants ----------------
#define INV8F   0.3535533905932738f   // 1/sqrt(8)
#define INV64F  0.125f                // 1/sqrt(64)
#define INV128F 0.08838834764831845f  // 1/sqrt(128)
#define INVNN   0.28867513459481287f  // 1/sqrt(12)
#define SQRT3F  1.7320508075688772f
#define SQRT2F  1.4142135623730951f
#define PI_F    3.14159265358979323846f

// =====================================================================
// Kernel 1: per-node "up" linear + species-indexed skip connection
// warp per node, 8 warps/block
// =====================================================================
__global__ void k_node_up(const float* __restrict__ ns, const float* __restrict__ nv,
                          const int* __restrict__ specie,
                          const float* __restrict__ Wus, const float* __restrict__ Wuv,
                          const float* __restrict__ Wss, const float* __restrict__ Wsv)
{
    __shared__ __align__(16) float xs[8][64];
    __shared__ __align__(16) float xv[8][192];
    int w = threadIdx.x >> 5, t = threadIdx.x & 31;
    int n = blockIdx.x * 8 + w;
    if (n >= N_NODES) return;

    xs[w][t]      = __ldg(ns + n * 64 + t);
    xs[w][t + 32] = __ldg(ns + n * 64 + t + 32);
#pragma unroll
    for (int q = 0; q < 6; q++)
        xv[w][t + 32 * q] = __ldg(nv + n * 192 + t + 32 * q);
    __syncwarp();

    int sp = __ldg(specie + n);
    const float* Ws = Wss + sp * 64 * 128;
    const float* Wv = Wsv + sp * 64 * 64;

    // h_s (2 outputs) and h_v (2 outputs x 3 comps)
    float a0 = 0.f, a1 = 0.f;
    float b[2][3] = {{0.f,0.f,0.f},{0.f,0.f,0.f}};
#pragma unroll 4
    for (int i = 0; i < 64; i++) {
        float x = xs[w][i];
        a0 += x * __ldg(Wus + i * 64 + t);
        a1 += x * __ldg(Wus + i * 64 + t + 32);
        float wv0 = __ldg(Wuv + i * 64 + t);
        float wv1 = __ldg(Wuv + i * 64 + t + 32);
        float xv0 = xv[w][i * 3 + 0], xv1 = xv[w][i * 3 + 1], xv2 = xv[w][i * 3 + 2];
        b[0][0] += xv0 * wv0; b[0][1] += xv1 * wv0; b[0][2] += xv2 * wv0;
        b[1][0] += xv0 * wv1; b[1][1] += xv1 * wv1; b[1][2] += xv2 * wv1;
    }
    g_hs[n * 64 + t]      = a0 * INV64F;
    g_hs[n * 64 + t + 32] = a1 * INV64F;
#pragma unroll
    for (int c = 0; c < 3; c++) {
        g_hv[c * NPLANE + n * 64 + t]      = b[0][c] * INV64F;
        g_hv[c * NPLANE + n * 64 + t + 32] = b[1][c] * INV64F;
    }

    // sc_s (4 outputs of 128) and sc_v (2 outputs x 3 comps)
    float s4[4] = {0.f,0.f,0.f,0.f};
    float c6[2][3] = {{0.f,0.f,0.f},{0.f,0.f,0.f}};
#pragma unroll 4
    for (int i = 0; i < 64; i++) {
        float x = xs[w][i];
#pragma unroll
        for (int q = 0; q < 4; q++)
            s4[q] += x * __ldg(Ws + i * 128 + t + 32 * q);
        float w0 = __ldg(Wv + i * 64 + t);
        float w1 = __ldg(Wv + i * 64 + t + 32);
        float xv0 = xv[w][i * 3 + 0], xv1 = xv[w][i * 3 + 1], xv2 = xv[w][i * 3 + 2];
        c6[0][0] += xv0 * w0; c6[0][1] += xv1 * w0; c6[0][2] += xv2 * w0;
        c6[1][0] += xv0 * w1; c6[1][1] += xv1 * w1; c6[1][2] += xv2 * w1;
    }
    float* sc = g_sc + (size_t)n * 320;
#pragma unroll
    for (int q = 0; q < 4; q++) sc[t + 32 * q] = s4[q] * INV64F;
#pragma unroll
    for (int c = 0; c < 3; c++) {
        sc[128 + t * 3 + c]        = c6[0][c] * INV64F;
        sc[128 + (t + 32) * 3 + c] = c6[1][c] * INV64F;
    }
}

// =====================================================================
// Kernel 2: edge kernel — radial MLP + tensor-product message + scatter
// warp handles 4 consecutive edges (amortizes W2/W3 reads 4x); 4 warps/block
// =====================================================================
#define EPW 4
#define K2W 4
__global__ void __launch_bounds__(128) k_edge(
    const float* __restrict__ vectors, const int* __restrict__ senders,
    const int* __restrict__ receivers, const float* __restrict__ W1,
    const float* __restrict__ W2, const float* __restrict__ W3)
{
    __shared__ float rb_sm[K2W][EPW][8];
    __shared__ float len_sm[K2W][EPW];
    __shared__ float h1_sm[K2W][EPW][64];
    __shared__ float h2_sm[K2W][EPW][64];
    __shared__ __align__(16) float mix_sm[K2W][EPW][256];

    int w = threadIdx.x >> 5, t = threadIdx.x & 31;
    int e0 = (blockIdx.x * K2W + w) * EPW;
    if (e0 >= N_EDGES) return;

    // ---- phase 0: radial basis, distributed (edge = t/8, k = t%8) ----
    {
        int el = t >> 3, k = t & 7;
        int e = e0 + el;
        float v0 = __ldg(vectors + e * 3 + 0);
        float v1 = __ldg(vectors + e * 3 + 1);
        float v2 = __ldg(vectors + e * 3 + 2);
        float len = sqrtf(v0 * v0 + v1 * v1 + v2 * v2);
        float x = len;
        float x2 = x * x, x3 = x2 * x, x6 = x3 * x3, x7 = x6 * x, x8 = x7 * x;
        float env = (x < 1.f) ? (1.f - 28.f * x6 + 48.f * x7 - 21.f * x8) : 0.f;
        float safe = (len == 0.f) ? 1.f : len;
        float rb = (len == 0.f) ? 0.f
                 : SQRT2F * sinf((float)(k + 1) * PI_F * len) / safe * env;
        rb_sm[w][el][k] = rb;
        if (k == 0) len_sm[w][el] = len;
    }
    __syncwarp();

    // ---- phase 1: h1 = swish(rb @ W1 * INV8) ----
    {
        float w1a[8], w1b[8];
#pragma unroll
        for (int k = 0; k < 8; k++) {
            w1a[k] = __ldg(W1 + k * 64 + t);
            w1b[k] = __ldg(W1 + k * 64 + t + 32);
        }
#pragma unroll
        for (int e = 0; e < EPW; e++) {
            float a = 0.f, b = 0.f;
#pragma unroll
            for (int k = 0; k < 8; k++) {
                float r = rb_sm[w][e][k];
                a += r * w1a[k]; b += r * w1b[k];
            }
            h1_sm[w][e][t]      = swishf(a * INV8F);
            h1_sm[w][e][t + 32] = swishf(b * INV8F);
        }
    }
    __syncwarp();

    // ---- phase 2: h2 = swish(h1 @ W2 * INV64) ----
    {
        float a[EPW] = {0.f,0.f,0.f,0.f}, b[EPW] = {0.f,0.f,0.f,0.f};
#pragma unroll 4
        for (int i = 0; i < 64; i++) {
            float wa = __ldg(W2 + i * 64 + t);
            float wb = __ldg(W2 + i * 64 + t + 32);
#pragma unroll
            for (int e = 0; e < EPW; e++) {
                float h = h1_sm[w][e][i];
                a[e] += h * wa; b[e] += h * wb;
            }
        }
#pragma unroll
        for (int e = 0; e < EPW; e++) {
            h2_sm[w][e][t]      = swishf(a[e] * INV64F);
            h2_sm[w][e][t + 32] = swishf(b[e] * INV64F);
        }
    }
    __syncwarp();

    // ---- phase 3: mix = h2 @ W3 * INV64  (256 outputs; lane t does t+32j) ----
    {
        float acc[8][EPW];
#pragma unroll
        for (int j = 0; j < 8; j++)
#pragma unroll
            for (int e = 0; e < EPW; e++) acc[j][e] = 0.f;
#pragma unroll 2
        for (int i = 0; i < 64; i++) {
            float h[EPW];
#pragma unroll
            for (int e = 0; e < EPW; e++) h[e] = h2_sm[w][e][i];
#pragma unroll
            for (int j = 0; j < 8; j++) {
                float ww = __ldg(W3 + i * 256 + t + 32 * j);
#pragma unroll
                for (int e = 0; e < EPW; e++) acc[j][e] += h[e] * ww;
            }
        }
#pragma unroll
        for (int j = 0; j < 8; j++)
#pragma unroll
            for (int e = 0; e < EPW; e++)
                mix_sm[w][e][t + 32 * j] = acc[j][e] * INV64F;
    }
    __syncwarp();

    // ---- phase 4: gather from sender, CG tensor product, scatter-add ----
#pragma unroll 1
    for (int el = 0; el < EPW; el++) {
        int e = e0 + el;
        int s = __ldg(senders + e);
        int r = __ldg(receivers + e);
        float len = len_sm[w][el];
        float inv = 1.f / ((len == 0.f) ? 1.f : len);
        float u0 = __ldg(vectors + e * 3 + 0) * inv;
        float u1 = __ldg(vectors + e * 3 + 1) * inv;
        float u2 = __ldg(vectors + e * 3 + 2) * inv;
        float y0 = SQRT3F * u0, y1 = SQRT3F * u1, y2 = SQRT3F * u2;

        int j = 4 * (t & 15);
        const float4 ms  = *(const float4*)(g_hs +               s * 64 + j);
        const float4 mv0 = *(const float4*)(g_hv + 0 * NPLANE + s * 64 + j);
        const float4 mv1 = *(const float4*)(g_hv + 1 * NPLANE + s * 64 + j);
        const float4 mv2 = *(const float4*)(g_hv + 2 * NPLANE + s * 64 + j);

        const float* mx = mix_sm[w][el];
        float4 m1 = *(const float4*)(mx + 4 * t);        // scalar mix
        float4 m2 = *(const float4*)(mx + 128 + 4 * t);  // vector mix

        float4 os, ov0, ov1, ov2;
        if (t < 16) {
            os  = make_float4(ms.x * m1.x, ms.y * m1.y, ms.z * m1.z, ms.w * m1.w);
            ov0 = make_float4(mv0.x * m2.x, mv0.y * m2.y, mv0.z * m2.z, mv0.w * m2.w);
            ov1 = make_float4(mv1.x * m2.x, mv1.y * m2.y, mv1.z * m2.z, mv1.w * m2.w);
            ov2 = make_float4(mv2.x * m2.x, mv2.y * m2.y, mv2.z * m2.z, mv2.w * m2.w);
        } else {
            // tp_0e = dot(m_v, Y)/sqrt3 = dot(m_v, u)
            float tpx = mv0.x * u0 + mv1.x * u1 + mv2.x * u2;
            float tpy = mv0.y * u0 + mv1.y * u1 + mv2.y * u2;
            float tpz = mv0.z * u0 + mv1.z * u1 + mv2.z * u2;
            float tpw = mv0.w * u0 + mv1.w * u1 + mv2.w * u2;
            os  = make_float4(tpx * m1.x, tpy * m1.y, tpz * m1.z, tpw * m1.w);
            // tp_1o = m_s * Y
            ov0 = make_float4(ms.x * y0 * m2.x, ms.y * y0 * m2.y, ms.z * y0 * m2.z, ms.w * y0 * m2.w);
            ov1 = make_float4(ms.x * y1 * m2.x, ms.y * y1 * m2.y, ms.z * y1 * m2.z, ms.w * y1 * m2.w);
            ov2 = make_float4(ms.x * y2 * m2.x, ms.y * y2 * m2.y, ms.z * y2 * m2.z, ms.w * y2 * m2.w);
        }
        float* base = g_agg + (size_t)r * 512;
        atomicAdd((float4*)(base + 4 * t),       os);
        atomicAdd((float4*)(base + 128 + 4 * t), ov0);
        atomicAdd((float4*)(base + 256 + 4 * t), ov1);
        atomicAdd((float4*)(base + 384 + 4 * t), ov2);
    }
}

// =====================================================================
// Kernel 3: per-node "down" linear + skip add + gate
// warp per node, 8 warps/block
// =====================================================================
__global__ void k_node_down(const float* __restrict__ Wds, const float* __restrict__ Wdv,
                            float* __restrict__ out)
{
    __shared__ __align__(16) float ag[8][512];
    int w = threadIdx.x >> 5, t = threadIdx.x & 31;
    int n = blockIdx.x * 8 + w;
    if (n >= N_NODES) return;

    const float4* src = (const float4*)(g_agg + (size_t)n * 512);
    float4* dst = (float4*)(ag[w]);
#pragma unroll
    for (int q = 0; q < 4; q++) dst[t + 32 * q] = src[t + 32 * q];
    __syncwarp();

    const float SCALE = INV128F * INVNN;

    float ds[4] = {0.f,0.f,0.f,0.f};
#pragma unroll 4
    for (int i = 0; i < 128; i++) {
        float x = ag[w][i];
#pragma unroll
        for (int q = 0; q < 4; q++)
            ds[q] += x * __ldg(Wds + i * 128 + t + 32 * q);
    }
    float dv[2][3] = {{0.f,0.f,0.f},{0.f,0.f,0.f}};
#pragma unroll 4
    for (int i = 0; i < 128; i++) {
        float w0 = __ldg(Wdv + i * 64 + t);
        float w1 = __ldg(Wdv + i * 64 + t + 32);
        float a0 = ag[w][128 + i], a1 = ag[w][256 + i], a2 = ag[w][384 + i];
        dv[0][0] += a0 * w0; dv[0][1] += a1 * w0; dv[0][2] += a2 * w0;
        dv[1][0] += a0 * w1; dv[1][1] += a1 * w1; dv[1][2] += a2 * w1;
    }

    const float* sc = g_sc + (size_t)n * 320;
#pragma unroll
    for (int q = 0; q < 4; q++) ds[q] = ds[q] * SCALE + sc[t + 32 * q];

    float g0 = swishf(ds[2]);   // gate for vector output o = t
    float g1 = swishf(ds[3]);   // gate for vector output o = t+32

    float* o = out + (size_t)n * 256;
    o[t]      = swishf(ds[0]);
    o[t + 32] = swishf(ds[1]);
#pragma unroll
    for (int c = 0; c < 3; c++) {
        float d0 = dv[0][c] * SCALE + sc[128 + t * 3 + c];
        float d1 = dv[1][c] * SCALE + sc[128 + (t + 32) * 3 + c];
        o[64 + t * 3 + c]        = d0 * g0;
        o[64 + (t + 32) * 3 + c] = d1 * g1;
    }
}

// =====================================================================
extern "C" void kernel_launch(void* const* d_in, const int* in_sizes, int n_in,
                              void* d_out, int out_size)
{
    const float* vectors      = (const float*)d_in[0];
    const float* node_scalars = (const float*)d_in[1];
    const float* node_vectors = (const float*)d_in[2];
    const int*   node_specie  = (const int*)  d_in[3];
    const int*   senders      = (const int*)  d_in[4];
    const int*   receivers    = (const int*)  d_in[5];
    const float* W_up_s       = (const float*)d_in[6];
    const float* W_up_v       = (const float*)d_in[7];
    const float* W_skip_s     = (const float*)d_in[8];
    const float* W_skip_v     = (const float*)d_in[9];
    const float* W_mlp1       = (const float*)d_in[10];
    const float* W_mlp2       = (const float*)d_in[11];
    const float* W_mlp3       = (const float*)d_in[12];
    const float* W_down_s     = (const float*)d_in[13];
    const float* W_down_v     = (const float*)d_in[14];
    float* out = (float*)d_out;

    void* aggp = nullptr;
    cudaGetSymbolAddress(&aggp, g_agg);
    cudaMemsetAsync(aggp, 0, (size_t)N_NODES * 512 * sizeof(float));

    k_node_up<<<(N_NODES + 7) / 8, 256>>>(node_scalars, node_vectors, node_specie,
                                          W_up_s, W_up_v, W_skip_s, W_skip_v);
    k_edge<<<N_EDGES / (K2W * EPW), 128>>>(vectors, senders, receivers,
                                           W_mlp1, W_mlp2, W_mlp3);
    k_node_down<<<(N_NODES + 7) / 8, 256>>>(W_down_s, W_down_v, out);
}